// round 5
// baseline (speedup 1.0000x reference)
#include <cuda_runtime.h>
#include <math_constants.h>

// RoIPool: feature_map [B=2, H=50, W=50, C=256] f32, rpn_pred [B=2, N=128, 4] f32
// out [B, N, 7, 7, C] f32.
//   x1=(int)(W*p0); y1=(int)(H*p1); x2=(int)(W*p2); y2=(int)(H*p3)
//   sw=(x2-x1)/7; sh=(y2-y1)/7   (in [1,4] by input construction)
//   out[b,n,i,j,c] = max_{r<sh,t<sw} fm[b, y1+i*sh+r, x1+j*sw+t, c]
// Bounds: x1+7*sw-1 <= x2-1 <= 49 (same for y) -> reference clip is dead code.
//
// CTA = (bin-pair, n, b), 64 threads, 4 channels x 2 bins per thread.
// All window loads are BRANCHLESS predicated @P LDG into -inf-initialized
// registers, followed by unconditional fmax: one basic block -> ptxas
// front-batches ~30 loads -> single L2-latency exposure per thread.

#define POOL 7
#define NROIS 128
#define BB 2
#define HH 50
#define WW 50
#define CC 256
#define C4 (CC / 4)   // 64 float4 per pixel
#define NBINS (POOL * POOL)       // 49
#define NPAIR ((NBINS + 1) / 2)   // 25

__global__ __launch_bounds__(64) void roi_pool_kernel(
    const float4* __restrict__ fm,     // [B*H*W*C4] float4
    const float4* __restrict__ rois,   // [B*N] float4 (x1,y1,x2,y2)
    float4*       __restrict__ out)    // [B*N*49*C4] float4
{
    const int pb = blockIdx.x;         // 0..24 bin pair
    const int n  = blockIdx.y;         // roi
    const int b  = blockIdx.z;         // batch
    const int c4 = threadIdx.x;        // 0..63 -> 4 channels

    const int bin0 = pb * 2;
    const int bin1 = bin0 + 1;
    const bool has1 = (bin1 < NBINS);

    // Single 128-bit ROI load.
    const float4 rp = __ldg(rois + b * NROIS + n);
    const int x1 = (int)(WW * rp.x);
    const int y1 = (int)(HH * rp.y);
    const int x2 = (int)(WW * rp.z);
    const int y2 = (int)(HH * rp.w);
    const int sw = (x2 - x1) / POOL;   // in [1,4]
    const int sh = (y2 - y1) / POOL;   // in [1,4]

    const int i0 = bin0 / POOL, j0 = bin0 - i0 * POOL;
    const int i1 = bin1 / POOL, j1 = bin1 - i1 * POOL;

    const float4* fmb = fm + (b * HH * WW) * C4 + c4;
    const float4* base0 = fmb + ((y1 + i0 * sh) * WW + (x1 + j0 * sw)) * C4;
    // For the odd trailing bin (bin 49 doesn't exist) alias base1 -> base0 so
    // speculative loads stay in-bounds; the result is simply not stored.
    const float4* base1 = has1
        ? fmb + ((y1 + i1 * sh) * WW + (x1 + j1 * sw)) * C4
        : base0;

    const float NEG = -CUDART_INF_F;

    // (0,0) always valid: init maxima with unconditional loads.
    float4 m0 = __ldg(base0);
    float4 m1 = __ldg(base1);

    #pragma unroll
    for (int r = 0; r < 4; ++r) {
        #pragma unroll
        for (int t = 0; t < 4; ++t) {
            if (r == 0 && t == 0) continue;
            const int off = (r * WW + t) * C4;
            // Branchless: predicated loads, unconditional fmax.
            float4 v0 = make_float4(NEG, NEG, NEG, NEG);
            float4 v1 = make_float4(NEG, NEG, NEG, NEG);
            const bool ok = (r < sh) & (t < sw);
            if (ok) v0 = __ldg(base0 + off);
            if (ok) v1 = __ldg(base1 + off);
            m0.x = fmaxf(m0.x, v0.x);
            m0.y = fmaxf(m0.y, v0.y);
            m0.z = fmaxf(m0.z, v0.z);
            m0.w = fmaxf(m0.w, v0.w);
            m1.x = fmaxf(m1.x, v1.x);
            m1.y = fmaxf(m1.y, v1.y);
            m1.z = fmaxf(m1.z, v1.z);
            m1.w = fmaxf(m1.w, v1.w);
        }
    }

    float4* obase = out + ((b * NROIS + n) * NBINS + bin0) * C4 + c4;
    obase[0] = m0;
    if (has1) obase[C4] = m1;
}

extern "C" void kernel_launch(void* const* d_in, const int* in_sizes, int n_in,
                              void* d_out, int out_size) {
    const float4* fm   = (const float4*)d_in[0];  // feature_map
    const float4* rois = (const float4*)d_in[1];  // rpn_pred as float4
    float4*       out  = (float4*)d_out;

    dim3 grid(NPAIR, NROIS, BB);
    roi_pool_kernel<<<grid, 64>>>(fm, rois, out);
}

// round 6
// speedup vs baseline: 1.1195x; 1.1195x over previous
#include <cuda_runtime.h>
#include <math_constants.h>

// RoIPool: feature_map [B=2, H=50, W=50, C=256] f32, rpn_pred [B=2, N=128, 4] f32
// out [B, N, 7, 7, C] f32.
//   x1=(int)(W*p0); y1=(int)(H*p1); x2=(int)(W*p2); y2=(int)(H*p3)
//   sw=(x2-x1)/7; sh=(y2-y1)/7   (in [1,4] by input construction)
//   out[b,n,i,j,c] = max_{r<sh,t<sw} fm[b, y1+i*sh+r, x1+j*sw+t, c]
// Bounds: x1+7*sw-1 <= x2-1 <= 49 (same for y) -> reference clip is dead code.
//
// CTA = (bin-pair, n, b), 64 threads, 4 channels x 2 bins per thread.
// (sh,sw) are CTA-uniform -> 16-way warp-uniform dispatch into fully
// specialized bodies: exact load/fmax count, compile-time immediate load
// offsets (zero per-load ALU), no divergence frames.

#define POOL 7
#define NROIS 128
#define BB 2
#define HH 50
#define WW 50
#define CC 256
#define C4 (CC / 4)   // 64 float4 per pixel
#define NBINS (POOL * POOL)       // 49
#define NPAIR ((NBINS + 1) / 2)   // 25

__device__ __forceinline__ void fmax4(float4& m, const float4 v) {
    m.x = fmaxf(m.x, v.x);
    m.y = fmaxf(m.y, v.y);
    m.z = fmaxf(m.z, v.z);
    m.w = fmaxf(m.w, v.w);
}

// Exact SHxSW window max for two bins. All offsets compile-time immediates.
// Loads grouped per row -> up to 2*SW independent LDG.128 in flight per group.
template<int SH, int SW>
__device__ __forceinline__ void window_pair(const float4* __restrict__ base0,
                                            const float4* __restrict__ base1,
                                            float4& m0, float4& m1) {
    #pragma unroll
    for (int r = 0; r < SH; ++r) {
        float4 a0[SW], a1[SW];
        #pragma unroll
        for (int t = 0; t < SW; ++t) {
            a0[t] = __ldg(base0 + (r * WW + t) * C4);
            a1[t] = __ldg(base1 + (r * WW + t) * C4);
        }
        #pragma unroll
        for (int t = 0; t < SW; ++t) {
            fmax4(m0, a0[t]);
            fmax4(m1, a1[t]);
        }
    }
}

__global__ __launch_bounds__(64) void roi_pool_kernel(
    const float4* __restrict__ fm,     // [B*H*W*C4] float4
    const float4* __restrict__ rois,   // [B*N] float4 (x1,y1,x2,y2)
    float4*       __restrict__ out)    // [B*N*49*C4] float4
{
    const int pb = blockIdx.x;         // 0..24 bin pair
    const int n  = blockIdx.y;         // roi
    const int b  = blockIdx.z;         // batch
    const int c4 = threadIdx.x;        // 0..63 -> 4 channels

    const int bin0 = pb * 2;
    const int bin1 = bin0 + 1;
    const bool has1 = (bin1 < NBINS);

    const float4 rp = __ldg(rois + b * NROIS + n);
    const int x1 = (int)(WW * rp.x);
    const int y1 = (int)(HH * rp.y);
    const int x2 = (int)(WW * rp.z);
    const int y2 = (int)(HH * rp.w);
    const int sw = (x2 - x1) / POOL;   // in [1,4]
    const int sh = (y2 - y1) / POOL;   // in [1,4]

    const int i0 = bin0 / POOL, j0 = bin0 - i0 * POOL;
    const int i1 = bin1 / POOL, j1 = bin1 - i1 * POOL;

    const float4* fmb = fm + (b * HH * WW) * C4 + c4;
    const float4* base0 = fmb + ((y1 + i0 * sh) * WW + (x1 + j0 * sw)) * C4;
    // Odd trailing bin (bin 49 doesn't exist): alias base1 -> base0 (safe loads,
    // result not stored).
    const float4* base1 = has1
        ? fmb + ((y1 + i1 * sh) * WW + (x1 + j1 * sw)) * C4
        : base0;

    const float NEG = -CUDART_INF_F;
    float4 m0 = make_float4(NEG, NEG, NEG, NEG);
    float4 m1 = make_float4(NEG, NEG, NEG, NEG);

    // Warp-uniform 16-way dispatch (sh, sw are the same for every thread in
    // the CTA -> no divergence).
    const int code = (sh - 1) * 4 + (sw - 1);
    switch (code) {
        case  0: window_pair<1,1>(base0, base1, m0, m1); break;
        case  1: window_pair<1,2>(base0, base1, m0, m1); break;
        case  2: window_pair<1,3>(base0, base1, m0, m1); break;
        case  3: window_pair<1,4>(base0, base1, m0, m1); break;
        case  4: window_pair<2,1>(base0, base1, m0, m1); break;
        case  5: window_pair<2,2>(base0, base1, m0, m1); break;
        case  6: window_pair<2,3>(base0, base1, m0, m1); break;
        case  7: window_pair<2,4>(base0, base1, m0, m1); break;
        case  8: window_pair<3,1>(base0, base1, m0, m1); break;
        case  9: window_pair<3,2>(base0, base1, m0, m1); break;
        case 10: window_pair<3,3>(base0, base1, m0, m1); break;
        case 11: window_pair<3,4>(base0, base1, m0, m1); break;
        case 12: window_pair<4,1>(base0, base1, m0, m1); break;
        case 13: window_pair<4,2>(base0, base1, m0, m1); break;
        case 14: window_pair<4,3>(base0, base1, m0, m1); break;
        default: window_pair<4,4>(base0, base1, m0, m1); break;
    }

    float4* obase = out + ((b * NROIS + n) * NBINS + bin0) * C4 + c4;
    obase[0] = m0;
    if (has1) obase[C4] = m1;
}

extern "C" void kernel_launch(void* const* d_in, const int* in_sizes, int n_in,
                              void* d_out, int out_size) {
    const float4* fm   = (const float4*)d_in[0];  // feature_map
    const float4* rois = (const float4*)d_in[1];  // rpn_pred as float4
    float4*       out  = (float4*)d_out;

    dim3 grid(NPAIR, NROIS, BB);
    roi_pool_kernel<<<grid, 64>>>(fm, rois, out);
}

// round 7
// speedup vs baseline: 1.1429x; 1.0208x over previous
#include <cuda_runtime.h>
#include <math_constants.h>

// RoIPool: feature_map [B=2, H=50, W=50, C=256] f32, rpn_pred [B=2, N=128, 4] f32
// out [B, N, 7, 7, C] f32.
//   x1=(int)(W*p0); y1=(int)(H*p1); x2=(int)(W*p2); y2=(int)(H*p3)
//   sw=(x2-x1)/7; sh=(y2-y1)/7   (in [1,4] by input construction)
//   out[b,n,i,j,c] = max_{r<sh,t<sw} fm[b, y1+i*sh+r, x1+j*sw+t, c]
// Bounds: x1+7*sw-1 <= x2-1 <= 49 (same for y) -> reference clip is dead code.
//
// CTA = (pair-group, n, b): 320 threads = 5 independent 64-thread slots, one
// bin-pair per slot (5*5 groups... grid.x=5 covers pairs 0..24 with slot).
// Per-thread body identical to R6: 16-way (sh,sw)-specialized, exact
// load/fmax count, compile-time immediate offsets. Bigger CTAs -> warp-limited
// residency (60 warps/SM) instead of 32-CTA-slot-limited (34 warps/SM).

#define POOL 7
#define NROIS 128
#define BB 2
#define HH 50
#define WW 50
#define CC 256
#define C4 (CC / 4)   // 64 float4 per pixel
#define NBINS (POOL * POOL)       // 49
#define NPAIR ((NBINS + 1) / 2)   // 25
#define SLOTS 5
#define THREADS (SLOTS * 64)      // 320

__device__ __forceinline__ void fmax4(float4& m, const float4 v) {
    m.x = fmaxf(m.x, v.x);
    m.y = fmaxf(m.y, v.y);
    m.z = fmaxf(m.z, v.z);
    m.w = fmaxf(m.w, v.w);
}

// Exact SHxSW window max for two bins. All offsets compile-time immediates.
template<int SH, int SW>
__device__ __forceinline__ void window_pair(const float4* __restrict__ base0,
                                            const float4* __restrict__ base1,
                                            float4& m0, float4& m1) {
    #pragma unroll
    for (int r = 0; r < SH; ++r) {
        float4 a0[SW], a1[SW];
        #pragma unroll
        for (int t = 0; t < SW; ++t) {
            a0[t] = __ldg(base0 + (r * WW + t) * C4);
            a1[t] = __ldg(base1 + (r * WW + t) * C4);
        }
        #pragma unroll
        for (int t = 0; t < SW; ++t) {
            fmax4(m0, a0[t]);
            fmax4(m1, a1[t]);
        }
    }
}

__global__ __launch_bounds__(THREADS) void roi_pool_kernel(
    const float4* __restrict__ fm,     // [B*H*W*C4] float4
    const float4* __restrict__ rois,   // [B*N] float4 (x1,y1,x2,y2)
    float4*       __restrict__ out)    // [B*N*49*C4] float4
{
    const int slot = threadIdx.x >> 6;          // 0..4
    const int c4   = threadIdx.x & 63;          // 0..63 -> 4 channels
    const int pb   = blockIdx.x * SLOTS + slot; // 0..24 bin pair
    const int n    = blockIdx.y;                // roi
    const int b    = blockIdx.z;                // batch

    const int bin0 = pb * 2;
    const int bin1 = bin0 + 1;
    const bool has1 = (bin1 < NBINS);

    const float4 rp = __ldg(rois + b * NROIS + n);
    const int x1 = (int)(WW * rp.x);
    const int y1 = (int)(HH * rp.y);
    const int x2 = (int)(WW * rp.z);
    const int y2 = (int)(HH * rp.w);
    const int sw = (x2 - x1) / POOL;   // in [1,4]
    const int sh = (y2 - y1) / POOL;   // in [1,4]

    const int i0 = bin0 / POOL, j0 = bin0 - i0 * POOL;
    const int i1 = bin1 / POOL, j1 = bin1 - i1 * POOL;

    const float4* fmb = fm + (b * HH * WW) * C4 + c4;
    const float4* base0 = fmb + ((y1 + i0 * sh) * WW + (x1 + j0 * sw)) * C4;
    // Odd trailing bin (bin 49 doesn't exist): alias base1 -> base0 (loads stay
    // in-bounds; result simply not stored).
    const float4* base1 = has1
        ? fmb + ((y1 + i1 * sh) * WW + (x1 + j1 * sw)) * C4
        : base0;

    const float NEG = -CUDART_INF_F;
    float4 m0 = make_float4(NEG, NEG, NEG, NEG);
    float4 m1 = make_float4(NEG, NEG, NEG, NEG);

    // Warp-uniform 16-way dispatch (sh, sw identical for all threads in CTA).
    const int code = (sh - 1) * 4 + (sw - 1);
    switch (code) {
        case  0: window_pair<1,1>(base0, base1, m0, m1); break;
        case  1: window_pair<1,2>(base0, base1, m0, m1); break;
        case  2: window_pair<1,3>(base0, base1, m0, m1); break;
        case  3: window_pair<1,4>(base0, base1, m0, m1); break;
        case  4: window_pair<2,1>(base0, base1, m0, m1); break;
        case  5: window_pair<2,2>(base0, base1, m0, m1); break;
        case  6: window_pair<2,3>(base0, base1, m0, m1); break;
        case  7: window_pair<2,4>(base0, base1, m0, m1); break;
        case  8: window_pair<3,1>(base0, base1, m0, m1); break;
        case  9: window_pair<3,2>(base0, base1, m0, m1); break;
        case 10: window_pair<3,3>(base0, base1, m0, m1); break;
        case 11: window_pair<3,4>(base0, base1, m0, m1); break;
        case 12: window_pair<4,1>(base0, base1, m0, m1); break;
        case 13: window_pair<4,2>(base0, base1, m0, m1); break;
        case 14: window_pair<4,3>(base0, base1, m0, m1); break;
        default: window_pair<4,4>(base0, base1, m0, m1); break;
    }

    float4* obase = out + ((b * NROIS + n) * NBINS + bin0) * C4 + c4;
    obase[0] = m0;
    if (has1) obase[C4] = m1;
}

extern "C" void kernel_launch(void* const* d_in, const int* in_sizes, int n_in,
                              void* d_out, int out_size) {
    const float4* fm   = (const float4*)d_in[0];  // feature_map
    const float4* rois = (const float4*)d_in[1];  // rpn_pred as float4
    float4*       out  = (float4*)d_out;

    dim3 grid(NPAIR / SLOTS, NROIS, BB);          // 5 x 128 x 2
    roi_pool_kernel<<<grid, THREADS>>>(fm, rois, out);
}